// round 1
// baseline (speedup 1.0000x reference)
#include <cuda_runtime.h>
#include <cstdint>
#include <math.h>

#define BB 64
#define MM 8192
#define VV 128
#define FEPS 1e-8f

// Scratch (device globals: no allocation allowed in kernel_launch)
__device__ float g_sim[BB * MM];   // 2 MB  similarity per slot
__device__ int   g_idx[BB * MM];   // 2 MB  compacted selected indices
__device__ float g_w[BB * MM];     // 2 MB  compacted selected weights
__device__ int   g_cnt[BB];        // selected count per batch

// ---- order-preserving float<->uint key mapping (larger float => larger key) ----
__device__ __forceinline__ unsigned f2k(float f) {
    unsigned b = __float_as_uint(f);
    return (b & 0x80000000u) ? ~b : (b | 0x80000000u);
}
__device__ __forceinline__ float k2f(unsigned u) {
    unsigned b = (u & 0x80000000u) ? (u ^ 0x80000000u) : ~u;
    return __uint_as_float(b);
}

// ============================================================================
// Pass 1: sim[b,m] = dot(mem[b,m]+eps, v[b]+eps) / max(||mem+eps|| * ||v+eps||, eps)
// One warp per row (V=128 floats = 32 lanes x float4). Grid: (M/8, B), 256 thr.
// ============================================================================
__global__ void __launch_bounds__(256) sim_kernel(const float* __restrict__ mem,
                                                  const float* __restrict__ vin) {
    __shared__ __align__(16) float sv[VV];
    __shared__ float s_nb;
    const int b   = blockIdx.y;
    const int tid = threadIdx.x;

    if (tid < VV) sv[tid] = vin[b * VV + tid] + FEPS;
    __syncthreads();
    if (tid < 32) {
        float s = 0.f;
        #pragma unroll
        for (int i = tid; i < VV; i += 32) { float x = sv[i]; s += x * x; }
        #pragma unroll
        for (int o = 16; o; o >>= 1) s += __shfl_xor_sync(0xffffffffu, s, o);
        if (tid == 0) s_nb = sqrtf(s);
    }
    __syncthreads();

    const int warp = tid >> 5;
    const int lane = tid & 31;
    const int m    = blockIdx.x * 8 + warp;

    const float4* row = reinterpret_cast<const float4*>(
        mem + ((size_t)b * MM + m) * VV);
    float4 x = row[lane];
    float4 q = reinterpret_cast<const float4*>(sv)[lane];

    float ax = x.x + FEPS, ay = x.y + FEPS, az = x.z + FEPS, aw = x.w + FEPS;
    float num = ax * q.x + ay * q.y + az * q.z + aw * q.w;
    float ss  = ax * ax + ay * ay + az * az + aw * aw;

    #pragma unroll
    for (int o = 16; o; o >>= 1) {
        num += __shfl_xor_sync(0xffffffffu, num, o);
        ss  += __shfl_xor_sync(0xffffffffu, ss, o);
    }

    if (lane == 0)
        g_sim[b * MM + m] = num / fmaxf(sqrtf(ss) * s_nb, FEPS);
}

// ============================================================================
// Pass 2: per-batch exact kth-largest via 4-round MSB radix select on uint keys,
// then compact all slots with key >= kth-key (== sim >= kth, tie-inclusive like
// the reference's `sim >= kth`). One block (256 threads) per batch.
// ============================================================================
__global__ void __launch_bounds__(256) select_kernel(const int* __restrict__ topk_ptr) {
    __shared__ unsigned keys[MM];   // 32 KB
    __shared__ int      hist[256];
    __shared__ unsigned s_prefix;
    __shared__ int      s_k;
    __shared__ int      s_cnt;

    const int b   = blockIdx.x;
    const int tid = threadIdx.x;

    for (int i = tid; i < MM; i += 256)
        keys[i] = f2k(g_sim[b * MM + i]);
    if (tid == 0) { s_prefix = 0u; s_k = *topk_ptr; s_cnt = 0; }
    __syncthreads();

    #pragma unroll
    for (int shift = 24; shift >= 0; shift -= 8) {
        hist[tid] = 0;
        __syncthreads();
        const unsigned pmask  = (shift == 24) ? 0u : (0xFFFFFFFFu << (shift + 8));
        const unsigned prefix = s_prefix;
        for (int i = tid; i < MM; i += 256) {
            unsigned u = keys[i];
            if ((u & pmask) == prefix)
                atomicAdd(&hist[(u >> shift) & 255], 1);
        }
        __syncthreads();
        if (tid == 0) {
            int k = s_k, run = 0, bin;
            for (bin = 255; bin > 0; bin--) {
                if (run + hist[bin] >= k) break;
                run += hist[bin];
            }
            s_k = k - run;
            s_prefix = prefix | ((unsigned)bin << shift);
        }
        __syncthreads();
    }

    const unsigned kthkey = s_prefix;

    for (int i = tid; i < MM; i += 256) {
        unsigned u = keys[i];
        if (u >= kthkey) {
            int p = atomicAdd(&s_cnt, 1);
            g_idx[b * MM + p] = i;
            g_w[b * MM + p]   = k2f(u);
        }
    }
    __syncthreads();
    if (tid == 0) g_cnt[b] = s_cnt;
}

// ============================================================================
// Pass 3: read[b,v] = sum_sel w*mem[b,m,v] + (sum_sel w^2) * v[b,v]
// One block (V=128 threads) per batch; ~64 selected rows, L2-hot.
// ============================================================================
__global__ void __launch_bounds__(VV) read_kernel(const float* __restrict__ mem,
                                                  const float* __restrict__ vin,
                                                  float* __restrict__ out) {
    const int b = blockIdx.x;
    const int t = threadIdx.x;
    const int n = g_cnt[b];

    float acc = 0.f, sw2 = 0.f;
    for (int i = 0; i < n; i++) {
        int   m = g_idx[b * MM + i];
        float w = g_w[b * MM + i];
        acc += w * mem[((size_t)b * MM + m) * VV + t];
        sw2 += w * w;
    }
    out[b * VV + t] = acc + sw2 * vin[b * VV + t];
}

// ============================================================================
extern "C" void kernel_launch(void* const* d_in, const int* in_sizes, int n_in,
                              void* d_out, int out_size) {
    const float* mem  = (const float*)d_in[0];   // (B, M, V) f32
    const float* vin  = (const float*)d_in[1];   // (B, V)    f32
    const int*   topk = (const int*)d_in[2];     // scalar    i32
    float*       out  = (float*)d_out;           // (B,1,1,V) f32

    sim_kernel<<<dim3(MM / 8, BB), 256>>>(mem, vin);
    select_kernel<<<BB, 256>>>(topk);
    read_kernel<<<BB, VV>>>(mem, vin, out);
}

// round 3
// speedup vs baseline: 2.2196x; 2.2196x over previous
#include <cuda_runtime.h>
#include <cstdint>
#include <math.h>

#define BB 64
#define MM 8192
#define VV 128
#define FEPS 1e-8f
#define SEL_CAP 1024

// Scratch (device globals: no allocation allowed in kernel_launch)
__device__ float g_sim[BB * MM];   // 2 MB similarity per slot

// ---- order-preserving float<->uint key mapping (larger float => larger key) ----
__device__ __forceinline__ unsigned f2k(float f) {
    unsigned b = __float_as_uint(f);
    return (b & 0x80000000u) ? ~b : (b | 0x80000000u);
}
__device__ __forceinline__ float k2f(unsigned u) {
    unsigned b = (u & 0x80000000u) ? (u ^ 0x80000000u) : ~u;
    return __uint_as_float(b);
}

// ============================================================================
// Pass 1: sim[b,m] = dot(mem[b,m]+eps, v[b]+eps) / max(||mem+eps||*||v+eps||, eps)
// Layout: 8 lanes per row, 4 rows per warp, 4 independent float4 loads per lane
// (MLP=4/thread, 16 loads in flight per warp), 3-level butterfly shared by all
// 4 rows of the warp. 256 threads -> 32 rows/tile, 2 tiles/block (unrolled).
// Grid: (MM/64, BB).
// ============================================================================
__global__ void __launch_bounds__(256) sim_kernel(const float* __restrict__ mem,
                                                  const float* __restrict__ vin) {
    __shared__ __align__(16) float sv[VV];
    __shared__ float s_nb;
    const int b   = blockIdx.y;
    const int tid = threadIdx.x;

    if (tid < VV) sv[tid] = vin[b * VV + tid] + FEPS;
    __syncthreads();
    if (tid < 32) {
        float s = 0.f;
        #pragma unroll
        for (int i = tid; i < VV; i += 32) { float x = sv[i]; s += x * x; }
        #pragma unroll
        for (int o = 16; o; o >>= 1) s += __shfl_xor_sync(0xffffffffu, s, o);
        if (tid == 0) s_nb = sqrtf(s);
    }
    __syncthreads();

    const float nb   = s_nb;
    const int   warp = tid >> 5;
    const int   lane = tid & 31;
    const int   rw   = lane >> 3;   // row within warp's 4-row group
    const int   s    = lane & 7;    // segment (float4 id base) within row

    const float4* svq = reinterpret_cast<const float4*>(sv);
    const float4 q0 = svq[s], q1 = svq[s + 8], q2 = svq[s + 16], q3 = svq[s + 24];

    #pragma unroll
    for (int it = 0; it < 2; it++) {
        const int m = blockIdx.x * 64 + it * 32 + warp * 4 + rw;
        const float4* row = reinterpret_cast<const float4*>(
            mem + ((size_t)b * MM + m) * VV);
        // 4 independent 16B loads -> MLP 4 per thread
        float4 x0 = row[s], x1 = row[s + 8], x2 = row[s + 16], x3 = row[s + 24];

        float num = 0.f, ss = 0.f;
        #define ACC(X, Q)                                             \
            { float a0 = X.x + FEPS, a1 = X.y + FEPS,                 \
                    a2 = X.z + FEPS, a3 = X.w + FEPS;                 \
              num += a0 * Q.x + a1 * Q.y + a2 * Q.z + a3 * Q.w;       \
              ss  += a0 * a0 + a1 * a1 + a2 * a2 + a3 * a3; }
        ACC(x0, q0) ACC(x1, q1) ACC(x2, q2) ACC(x3, q3)
        #undef ACC

        // reduce across the 8 lanes of this row (xor 1,2,4)
        #pragma unroll
        for (int o = 4; o; o >>= 1) {
            num += __shfl_xor_sync(0xffffffffu, num, o);
            ss  += __shfl_xor_sync(0xffffffffu, ss,  o);
        }
        if (s == 0)
            g_sim[b * MM + m] = num / fmaxf(sqrtf(ss) * nb, FEPS);
    }
}

// ============================================================================
// Pass 2 (fused select + read): per-batch exact kth-largest via 4-round 8-bit
// MSB radix select, compaction of sim >= kth into smem, then the read
//   out[b,:] = sum_sel w*mem[b,m,:] + (sum_sel w^2)*v[b,:]
// One block of 1024 threads per batch.
// ============================================================================
__global__ void __launch_bounds__(1024) select_read_kernel(
        const int* __restrict__ topk_ptr,
        const float* __restrict__ mem,
        const float* __restrict__ vin,
        float* __restrict__ out) {
    __shared__ unsigned keys[MM];        // 32 KB
    __shared__ int      hist[256];
    __shared__ int      wsum[8];
    __shared__ unsigned s_prefix;
    __shared__ int      s_k, s_cnt;
    __shared__ int      s_idx[SEL_CAP];
    __shared__ float    s_w[SEL_CAP];
    __shared__ float    s_part[8][VV];   // 4 KB partial read accumulators
    __shared__ float    s_sw2;

    const int b   = blockIdx.x;
    const int tid = threadIdx.x;

    for (int i = tid; i < MM; i += 1024)
        keys[i] = f2k(g_sim[b * MM + i]);
    if (tid == 0) { s_prefix = 0u; s_k = *topk_ptr; s_cnt = 0; }
    __syncthreads();

    #pragma unroll
    for (int shift = 24; shift >= 0; shift -= 8) {
        if (tid < 256) hist[tid] = 0;
        __syncthreads();
        const unsigned pmask  = (shift == 24) ? 0u : (0xFFFFFFFFu << (shift + 8));
        const unsigned prefix = s_prefix;
        for (int i = tid; i < MM; i += 1024) {
            unsigned u = keys[i];
            if ((u & pmask) == prefix)
                atomicAdd(&hist[(u >> shift) & 255], 1);
        }
        __syncthreads();
        // two-stage top-down scan: 8 warp sums, then <=40 serial steps
        if (tid < 256) {
            int v = hist[tid];
            #pragma unroll
            for (int o = 16; o; o >>= 1) v += __shfl_xor_sync(0xffffffffu, v, o);
            if ((tid & 31) == 0) wsum[tid >> 5] = v;
        }
        __syncthreads();
        if (tid == 0) {
            int k = s_k, run = 0, g;
            for (g = 7; g > 0; g--) {
                if (run + wsum[g] >= k) break;
                run += wsum[g];
            }
            int bin;
            for (bin = g * 32 + 31; bin > g * 32; bin--) {
                if (run + hist[bin] >= k) break;
                run += hist[bin];
            }
            s_k = k - run;
            s_prefix = prefix | ((unsigned)bin << shift);
        }
        __syncthreads();
    }

    const unsigned kthkey = s_prefix;
    for (int i = tid; i < MM; i += 1024) {
        unsigned u = keys[i];
        if (u >= kthkey) {
            int p = atomicAdd(&s_cnt, 1);
            if (p < SEL_CAP) { s_idx[p] = i; s_w[p] = k2f(u); }
        }
    }
    __syncthreads();

    int n = s_cnt; if (n > SEL_CAP) n = SEL_CAP;

    // sum of w^2 (one warp)
    if (tid < 32) {
        float sw2 = 0.f;
        for (int i = tid; i < n; i += 32) { float w = s_w[i]; sw2 += w * w; }
        #pragma unroll
        for (int o = 16; o; o >>= 1) sw2 += __shfl_xor_sync(0xffffffffu, sw2, o);
        if (tid == 0) s_sw2 = sw2;
    }

    // read: 8 groups of 128 threads accumulate over selected rows (L2-hot)
    const int vcol = tid & (VV - 1);
    const int grp  = tid >> 7;
    float acc = 0.f;
    for (int i = grp; i < n; i += 8) {
        int   m = s_idx[i];
        float w = s_w[i];
        acc += w * mem[((size_t)b * MM + m) * VV + vcol];
    }
    s_part[grp][vcol] = acc;
    __syncthreads();

    if (tid < VV) {
        float a = 0.f;
        #pragma unroll
        for (int g = 0; g < 8; g++) a += s_part[g][tid];
        out[b * VV + tid] = a + s_sw2 * vin[b * VV + tid];
    }
}

// ============================================================================
extern "C" void kernel_launch(void* const* d_in, const int* in_sizes, int n_in,
                              void* d_out, int out_size) {
    const float* mem  = (const float*)d_in[0];   // (B, M, V) f32
    const float* vin  = (const float*)d_in[1];   // (B, V)    f32
    const int*   topk = (const int*)d_in[2];     // scalar    i32
    float*       out  = (float*)d_out;           // (B,1,1,V) f32

    sim_kernel<<<dim3(MM / 64, BB), 256>>>(mem, vin);
    select_read_kernel<<<BB, 1024>>>(topk, mem, vin, out);
}